// round 12
// baseline (speedup 1.0000x reference)
#include <cuda_runtime.h>
#include <cstdint>
#include <cstddef>
#include <math_constants.h>

#define TT 1024
#define BB 512
#define VV 29
#define HH 64
#define GG 256          // 4*H
#define RR 4            // batch rows per block
#define NBLK 128        // 512 / 4
#define SOS_BIT (1u << 27)

// ---------------------------------------------------------------------------
// Device scratch
// ---------------------------------------------------------------------------
__device__ float g_h1[BB * HH];
__device__ float g_c1[BB * HH];
__device__ unsigned g_mask[TT + 1];            // per-step one-hot-union masks
__device__ unsigned g_cnt[TT + 1];             // per-step release counters

typedef unsigned long long u64;

// ---------------------------------------------------------------------------
// f32x2 packed-FMA helpers
// ---------------------------------------------------------------------------
__device__ __forceinline__ u64 ffma2(u64 a, u64 b, u64 c) {
    u64 d; asm("fma.rn.f32x2 %0, %1, %2, %3;" : "=l"(d) : "l"(a), "l"(b), "l"(c));
    return d;
}
__device__ __forceinline__ u64 fadd2(u64 a, u64 b) {
    u64 d; asm("add.rn.f32x2 %0, %1, %2;" : "=l"(d) : "l"(a), "l"(b));
    return d;
}
__device__ __forceinline__ u64 pk2(float lo, float hi) {
    u64 d; asm("mov.b64 %0, {%1, %2};" : "=l"(d) : "f"(lo), "f"(hi));
    return d;
}
__device__ __forceinline__ float f2sum(u64 a) {
    float lo, hi; asm("mov.b64 {%0, %1}, %2;" : "=f"(lo), "=f"(hi) : "l"(a));
    return lo + hi;
}
__device__ __forceinline__ unsigned ld_acq(const unsigned* p) {
    unsigned v;
    asm volatile("ld.global.acquire.gpu.u32 %0, [%1];" : "=r"(v) : "l"(p) : "memory");
    return v;
}
// Fast transcendentals (single-MUFU forms, limit-correct, rel err ~1e-6)
__device__ __forceinline__ float sigf(float x) {
    return __fdividef(1.0f, 1.0f + __expf(-x));
}
__device__ __forceinline__ float tanhf_fast(float x) {
    return 1.0f - __fdividef(2.0f, __expf(2.0f * x) + 1.0f);
}

// ---------------------------------------------------------------------------
// Init: reset masks + counters (deterministic graph replays)
// ---------------------------------------------------------------------------
__global__ void init_kernel() {
    int i = blockIdx.x * blockDim.x + threadIdx.x;
    if (i <= TT) {
        g_mask[i] = (i == 0) ? SOS_BIT : 0u;
        g_cnt[i]  = (i == 0) ? (unsigned)NBLK : 0u;
    }
}

// ---------------------------------------------------------------------------
// FUSED encoder: layer0 (V->H) and layer1 (H->H) in one pipelined kernel.
// Iteration `it` computes layer0 step `it` and layer1 step `it-1`.
// 512 threads: pair (2g, 2g+1) owns gate g of BOTH layers (k-split halves).
// Pointwise: tid<256 owns layer0 (c0), tid>=256 owns layer1 (c1) — concurrent.
// No g_y1 DRAM traffic: y flows through h0s in shared memory.
// ---------------------------------------------------------------------------
__global__ __launch_bounds__(512, 1) void enc_fused_kernel(
    const float* __restrict__ x_seq,
    const float* __restrict__ Wih0, const float* __restrict__ Whh0,
    const float* __restrict__ bih0, const float* __restrict__ bhh0,
    const float* __restrict__ Wih1, const float* __restrict__ Whh1,
    const float* __restrict__ bih1, const float* __restrict__ bhh1)
{
    __shared__ __align__(16) float xs[2][RR][32];
    __shared__ __align__(16) float h0s[RR * HH];
    __shared__ __align__(16) float h1s[RR * HH];
    __shared__ float g0s[RR][GG];
    __shared__ float g1s[RR][GG];

    const int tid  = threadIdx.x;
    const int g    = tid >> 1;
    const int half = tid & 1;
    const int kx0  = half * 16;
    const int kh0  = half * 32;
    const int r0   = blockIdx.x * RR;

    // layer0 weights: 8 + 16 u64; layer1: 16 + 16 u64  (56 u64 = 112 f32 regs)
    u64 wx0[8], wh0[16], wx1[16], wh1[16];
#pragma unroll
    for (int q = 0; q < 8; q++) {
        int k = kx0 + 2 * q;
        float a = (k < VV)     ? Wih0[g * VV + k]     : 0.0f;
        float b = (k + 1 < VV) ? Wih0[g * VV + k + 1] : 0.0f;
        wx0[q] = pk2(a, b);
    }
#pragma unroll
    for (int q = 0; q < 16; q++) {
        wh0[q] = pk2(Whh0[g * HH + kh0 + 2 * q], Whh0[g * HH + kh0 + 2 * q + 1]);
        wx1[q] = pk2(Wih1[g * HH + kh0 + 2 * q], Wih1[g * HH + kh0 + 2 * q + 1]);
        wh1[q] = pk2(Whh1[g * HH + kh0 + 2 * q], Whh1[g * HH + kh0 + 2 * q + 1]);
    }
    const float bias0 = half ? 0.0f : (bih0[g] + bhh0[g]);
    const float bias1 = half ? 0.0f : (bih1[g] + bhh1[g]);

    if (tid < 256) h0s[tid] = 0.0f; else h1s[tid - 256] = 0.0f;
    if (tid < 2 * RR * 3) {     // zero x pads in both buffers
        int b = tid / (RR * 3), r = (tid / 3) % RR, k = VV + tid % 3;
        xs[b][r][k] = 0.0f;
    }
    if (tid < RR * VV) {
        int row = tid / VV, v = tid % VV;
        xs[0][row][v] = x_seq[((size_t)0 * BB + r0 + row) * VV + v];
    }
    float c = 0.0f;      // c0 for tid<256, c1 for tid>=256
    __syncthreads();

    int cur = 0;
    for (int it = 0; it <= TT; it++) {
        // ---- Phase A: gates for layer0(step it) and layer1(step it-1) ----
        if (it < TT) {
#pragma unroll
            for (int row = 0; row < RR; row++) {
                const ulonglong2* xp = (const ulonglong2*)&xs[cur][row][kx0];
                const ulonglong2* hp = (const ulonglong2*)&h0s[row * HH + kh0];
                u64 a0 = 0ull, a1 = 0ull;
#pragma unroll
                for (int m = 0; m < 4; m++) {
                    ulonglong2 xv = xp[m];
                    a0 = ffma2(wx0[2 * m],     xv.x, a0);
                    a1 = ffma2(wx0[2 * m + 1], xv.y, a1);
                }
#pragma unroll
                for (int m = 0; m < 8; m++) {
                    ulonglong2 hv = hp[m];
                    a0 = ffma2(wh0[2 * m],     hv.x, a0);
                    a1 = ffma2(wh0[2 * m + 1], hv.y, a1);
                }
                float s = f2sum(fadd2(a0, a1)) + bias0;
                s += __shfl_xor_sync(0xffffffffu, s, 1);
                if (!half) g0s[row][g] = s;
            }
        }
        if (it >= 1) {
#pragma unroll
            for (int row = 0; row < RR; row++) {
                const ulonglong2* yp = (const ulonglong2*)&h0s[row * HH + kh0];
                const ulonglong2* hp = (const ulonglong2*)&h1s[row * HH + kh0];
                u64 a0 = 0ull, a1 = 0ull;
#pragma unroll
                for (int m = 0; m < 8; m++) {
                    ulonglong2 yv = yp[m];
                    a0 = ffma2(wx1[2 * m],     yv.x, a0);
                    a1 = ffma2(wx1[2 * m + 1], yv.y, a1);
                }
#pragma unroll
                for (int m = 0; m < 8; m++) {
                    ulonglong2 hv = hp[m];
                    a0 = ffma2(wh1[2 * m],     hv.x, a0);
                    a1 = ffma2(wh1[2 * m + 1], hv.y, a1);
                }
                float s = f2sum(fadd2(a0, a1)) + bias1;
                s += __shfl_xor_sync(0xffffffffu, s, 1);
                if (!half) g1s[row][g] = s;
            }
        }
        // prefetch next x tile
        if (it + 1 < TT && tid < RR * VV) {
            int row = tid / VV, v = tid % VV;
            xs[cur ^ 1][row][v] = x_seq[((size_t)(it + 1) * BB + r0 + row) * VV + v];
        }
        __syncthreads();

        // ---- Phase B: pointwise, both layers concurrently ----
        if (tid < 256) {
            if (it < TT) {
                int row = tid >> 6, j = tid & 63;
                float gi = g0s[row][j];
                float gf = g0s[row][64 + j];
                float gc = g0s[row][128 + j];
                float go = g0s[row][192 + j];
                c = sigf(gf) * c + sigf(gi) * tanhf_fast(gc);
                h0s[tid] = sigf(go) * tanhf_fast(c);
            }
        } else {
            if (it >= 1) {
                int t2 = tid - 256;
                int row = t2 >> 6, j = t2 & 63;
                float gi = g1s[row][j];
                float gf = g1s[row][64 + j];
                float gc = g1s[row][128 + j];
                float go = g1s[row][192 + j];
                c = sigf(gf) * c + sigf(gi) * tanhf_fast(gc);
                float h = sigf(go) * tanhf_fast(c);
                h1s[t2] = h;
                if (it == TT) {
                    g_h1[(size_t)r0 * HH + t2] = h;
                    g_c1[(size_t)r0 * HH + t2] = c;
                }
            }
        }
        __syncthreads();
        cur ^= 1;
    }
}

// ---------------------------------------------------------------------------
// Decoder: persistent, 128 blocks x 512 threads (R7/R11-proven structure).
// Pair (2g, 2g+1) owns gate g for BOTH cells (k-split halves).
// h2*Whh2 dot computed BEFORE the per-step spin to hide release latency.
// ---------------------------------------------------------------------------
__global__ __launch_bounds__(512, 1) void dec_kernel(
    const float* __restrict__ d1_Wih, const float* __restrict__ d1_Whh,
    const float* __restrict__ d1_bih, const float* __restrict__ d1_bhh,
    const float* __restrict__ d2_Wih, const float* __restrict__ d2_Whh,
    const float* __restrict__ d2_bih, const float* __restrict__ d2_bhh,
    const float* __restrict__ cls_W, const float* __restrict__ cls_b,
    float* __restrict__ out)
{
    __shared__ float wih1T[VV * GG];                 // [j][g] letc table
    __shared__ __align__(16) u64 clsP[32 * 32];      // [kpair][v] packed cls weights
    __shared__ __align__(16) float h1s[RR * HH];
    __shared__ __align__(16) float h2s[RR * HH];
    __shared__ float g1s[RR * GG];
    __shared__ float g2s[RR * GG];
    __shared__ __align__(16) float ps[RR * 32];
    __shared__ float clsb[32];

    const int tid  = threadIdx.x;
    const int g    = tid >> 1;
    const int half = tid & 1;
    const int ko   = half * 32;
    const int lane = tid & 31;
    const int r0   = blockIdx.x * RR;

    u64 whh1[16], wih2[16], whh2[16];
#pragma unroll
    for (int q = 0; q < 16; q++) {
        whh1[q] = pk2(d1_Whh[g * HH + ko + 2 * q], d1_Whh[g * HH + ko + 2 * q + 1]);
        wih2[q] = pk2(d2_Wih[g * HH + ko + 2 * q], d2_Wih[g * HH + ko + 2 * q + 1]);
        whh2[q] = pk2(d2_Whh[g * HH + ko + 2 * q], d2_Whh[g * HH + ko + 2 * q + 1]);
    }
    const float bias1 = half ? 0.0f : (d1_bih[g] + d1_bhh[g]);
    const float bias2 = half ? 0.0f : (d2_bih[g] + d2_bhh[g]);

    for (int i = tid; i < VV * GG; i += 512)
        wih1T[(i % VV) * GG + (i / VV)] = d1_Wih[i];
    for (int i = tid; i < VV * 32; i += 512) {
        int v = i >> 5, kk = i & 31;
        clsP[kk * 32 + v] = pk2(cls_W[v * HH + 2 * kk], cls_W[v * HH + 2 * kk + 1]);
    }
    if (tid < VV) clsb[tid] = cls_b[tid];
    if (tid < RR * 3) ps[(tid / 3) * 32 + VV + tid % 3] = -CUDART_INF_F;

    float c;
    if (tid < 256) {
        h1s[tid] = g_h1[(size_t)r0 * HH + tid];
        c        = g_c1[(size_t)r0 * HH + tid];
        h2s[tid] = 0.0f;
    } else {
        c = 0.0f;
    }
    __syncthreads();

    // letc j-range split across the pair (folds into the gate shfl-reduce)
    const int j0 = half ? 15 : 0;
    const int j1 = half ? VV : 15;

    for (int step = 0; step < TT; step++) {
        // ---- pre-phase: mask-independent h2 * Whh2 dot (hides spin) ----
        u64 acc2[RR];
#pragma unroll
        for (int row = 0; row < RR; row++) {
            const ulonglong2* hp = (const ulonglong2*)&h2s[row * HH + ko];
            u64 a0 = 0ull, a1 = 0ull;
#pragma unroll
            for (int m = 0; m < 8; m++) {
                ulonglong2 hv = hp[m];
                a0 = ffma2(whh2[2 * m],     hv.x, a0);
                a1 = ffma2(whh2[2 * m + 1], hv.y, a1);
            }
            acc2[row] = fadd2(a0, a1);
        }

        // ---- acquire this step's mask (lane 0 of each warp spins) ----
        unsigned mask;
        if (lane == 0) {
            while (ld_acq(&g_cnt[step]) < (unsigned)NBLK) { }
            mask = ld_acq(&g_mask[step]);
        }
        mask = __shfl_sync(0xffffffffu, mask, 0);

        // ---- cell1 gates: (letc-half + bias) + h1 * Whh1 (pair k-split) ----
        float ls = bias1;
        for (int j = j0; j < j1; j++)
            if ((mask >> j) & 1u) ls += wih1T[j * GG + g];
#pragma unroll
        for (int row = 0; row < RR; row++) {
            const ulonglong2* hp = (const ulonglong2*)&h1s[row * HH + ko];
            u64 a0 = 0ull, a1 = 0ull;
#pragma unroll
            for (int m = 0; m < 8; m++) {
                ulonglong2 hv = hp[m];
                a0 = ffma2(whh1[2 * m],     hv.x, a0);
                a1 = ffma2(whh1[2 * m + 1], hv.y, a1);
            }
            float s = f2sum(fadd2(a0, a1)) + ls;
            s += __shfl_xor_sync(0xffffffffu, s, 1);
            if (!half) g1s[row * GG + g] = s;
        }
        __syncthreads();

        // ---- cell1 pointwise (tid<256 owns c1) ----
        if (tid < 256) {
            int row = tid >> 6, j = tid & 63;
            float gi = g1s[row * GG + j];
            float gf = g1s[row * GG + 64 + j];
            float gc = g1s[row * GG + 128 + j];
            float go = g1s[row * GG + 192 + j];
            c = sigf(gf) * c + sigf(gi) * tanhf_fast(gc);
            h1s[tid] = sigf(go) * tanhf_fast(c);
        }
        __syncthreads();

        // ---- cell2 gates: h1_new * Wih2 + precomputed h2-dot ----
#pragma unroll
        for (int row = 0; row < RR; row++) {
            const ulonglong2* hp = (const ulonglong2*)&h1s[row * HH + ko];
            u64 a = acc2[row];
#pragma unroll
            for (int m = 0; m < 8; m++) {
                ulonglong2 hv = hp[m];
                a = ffma2(wih2[2 * m],     hv.x, a);
                a = ffma2(wih2[2 * m + 1], hv.y, a);
            }
            float s = f2sum(a) + bias2;
            s += __shfl_xor_sync(0xffffffffu, s, 1);
            if (!half) g2s[row * GG + g] = s;
        }
        __syncthreads();

        // ---- cell2 pointwise (tid>=256 owns c2) ----
        if (tid >= 256) {
            int t2 = tid - 256;
            int row = t2 >> 6, j = t2 & 63;
            float gi = g2s[row * GG + j];
            float gf = g2s[row * GG + 64 + j];
            float gc = g2s[row * GG + 128 + j];
            float go = g2s[row * GG + 192 + j];
            c = sigf(gf) * c + sigf(gi) * tanhf_fast(gc);
            h2s[t2] = sigf(go) * tanhf_fast(c);
        }
        __syncthreads();

        // ---- classifier (tid<256, pair k-split over 116 (row,v) pairs) ----
        if (tid < 256) {
            int p = tid >> 1;
            bool valid = p < RR * VV;
            int pc = valid ? p : 0;
            int row = pc / VV, v = pc - row * VV;
            const ulonglong2* hp = (const ulonglong2*)(&h2s[row * HH] + half * 32);
            u64 a = 0ull;
#pragma unroll
            for (int m = 0; m < 8; m++) {
                ulonglong2 hv = hp[m];
                a = ffma2(clsP[(half * 16 + 2 * m) * 32 + v],     hv.x, a);
                a = ffma2(clsP[(half * 16 + 2 * m + 1) * 32 + v], hv.y, a);
            }
            float s = f2sum(a) + (half ? 0.0f : clsb[v]);
            s += __shfl_xor_sync(0xffffffffu, s, 1);
            if (valid && !half) {
                ps[row * 32 + v] = s;
                out[((size_t)step * BB + r0 + row) * VV + v] = s;
            }
        }
        __syncthreads();

        // ---- argmax (warp 0) + global release for step+1 ----
        if (tid < 32) {
            int row = tid >> 3, sl = tid & 7;
            float4 vv = *(const float4*)&ps[row * 32 + sl * 4];
            float best = vv.x; int bi = sl * 4;
            if (vv.y > best) { best = vv.y; bi = sl * 4 + 1; }
            if (vv.z > best) { best = vv.z; bi = sl * 4 + 2; }
            if (vv.w > best) { best = vv.w; bi = sl * 4 + 3; }
#pragma unroll
            for (int off = 1; off <= 4; off <<= 1) {
                float ob = __shfl_xor_sync(0xffffffffu, best, off);
                int   oi = __shfl_xor_sync(0xffffffffu, bi,   off);
                if (ob > best || (ob == best && oi < bi)) { best = ob; bi = oi; }
            }
            unsigned bits = (sl == 0) ? (1u << bi) : 0u;
            bits |= __shfl_xor_sync(0xffffffffu, bits, 8);
            bits |= __shfl_xor_sync(0xffffffffu, bits, 16);
            if (tid == 0) {
                atomicOr(&g_mask[step + 1], bits);
                __threadfence();
                atomicAdd(&g_cnt[step + 1], 1u);
            }
        }
        // no trailing sync: next pre-phase only READS h2s (next write to any
        // shared buffer is g1s, which is behind this step's syncs)
    }
}

// ---------------------------------------------------------------------------
// Launch
// ---------------------------------------------------------------------------
extern "C" void kernel_launch(void* const* d_in, const int* in_sizes, int n_in,
                              void* d_out, int out_size)
{
    const float* input_seq = (const float*)d_in[0];
    const float* enc_Wih0  = (const float*)d_in[1];
    const float* enc_Whh0  = (const float*)d_in[2];
    const float* enc_bih0  = (const float*)d_in[3];
    const float* enc_bhh0  = (const float*)d_in[4];
    const float* enc_Wih1  = (const float*)d_in[5];
    const float* enc_Whh1  = (const float*)d_in[6];
    const float* enc_bih1  = (const float*)d_in[7];
    const float* enc_bhh1  = (const float*)d_in[8];
    const float* d1_Wih    = (const float*)d_in[9];
    const float* d1_Whh    = (const float*)d_in[10];
    const float* d1_bih    = (const float*)d_in[11];
    const float* d1_bhh    = (const float*)d_in[12];
    const float* d2_Wih    = (const float*)d_in[13];
    const float* d2_Whh    = (const float*)d_in[14];
    const float* d2_bih    = (const float*)d_in[15];
    const float* d2_bhh    = (const float*)d_in[16];
    const float* cls_W     = (const float*)d_in[17];
    const float* cls_b     = (const float*)d_in[18];
    float* out = (float*)d_out;

    init_kernel<<<3, 512>>>();
    enc_fused_kernel<<<NBLK, 512>>>(input_seq,
                                    enc_Wih0, enc_Whh0, enc_bih0, enc_bhh0,
                                    enc_Wih1, enc_Whh1, enc_bih1, enc_bhh1);
    dec_kernel<<<NBLK, 512>>>(d1_Wih, d1_Whh, d1_bih, d1_bhh,
                              d2_Wih, d2_Whh, d2_bih, d2_bhh,
                              cls_W, cls_b, out);
}

// round 13
// speedup vs baseline: 1.1760x; 1.1760x over previous
#include <cuda_runtime.h>
#include <cstdint>
#include <cstddef>
#include <math_constants.h>

#define TT 1024
#define BB 512
#define VV 29
#define HH 64
#define GG 256          // 4*H
#define RR 4            // batch rows per block
#define NBLK 128        // 512 / 4
#define SOS_BIT (1u << 27)
#define SENT 0xFFFFFFFFu   // sentinel: valid masks are <= 0x1FFFFFFF

// ---------------------------------------------------------------------------
// Device scratch
// ---------------------------------------------------------------------------
__device__ float g_y1[(size_t)TT * BB * HH];   // encoder layer0 output (134 MB)
__device__ float g_h1[BB * HH];
__device__ float g_c1[BB * HH];
// per-(step, block) published argmax-bit slots; sentinel = not yet written
__device__ __align__(16) unsigned g_slots[(TT + 1) * NBLK];

typedef unsigned long long u64;

// ---------------------------------------------------------------------------
// f32x2 packed-FMA helpers
// ---------------------------------------------------------------------------
__device__ __forceinline__ u64 ffma2(u64 a, u64 b, u64 c) {
    u64 d; asm("fma.rn.f32x2 %0, %1, %2, %3;" : "=l"(d) : "l"(a), "l"(b), "l"(c));
    return d;
}
__device__ __forceinline__ u64 fadd2(u64 a, u64 b) {
    u64 d; asm("add.rn.f32x2 %0, %1, %2;" : "=l"(d) : "l"(a), "l"(b));
    return d;
}
__device__ __forceinline__ u64 pk2(float lo, float hi) {
    u64 d; asm("mov.b64 %0, {%1, %2};" : "=l"(d) : "f"(lo), "f"(hi));
    return d;
}
__device__ __forceinline__ float f2sum(u64 a) {
    float lo, hi; asm("mov.b64 {%0, %1}, %2;" : "=f"(lo), "=f"(hi) : "l"(a));
    return lo + hi;
}
__device__ __forceinline__ uint4 ld_vol4(const unsigned* p) {
    uint4 v;
    asm volatile("ld.volatile.global.v4.u32 {%0,%1,%2,%3}, [%4];"
                 : "=r"(v.x), "=r"(v.y), "=r"(v.z), "=r"(v.w) : "l"(p) : "memory");
    return v;
}
__device__ __forceinline__ void st_rel(unsigned* p, unsigned v) {
    asm volatile("st.release.gpu.global.u32 [%0], %1;" :: "l"(p), "r"(v) : "memory");
}
// Fast transcendentals (single-MUFU forms, limit-correct, rel err ~1e-6)
__device__ __forceinline__ float sigf(float x) {
    return __fdividef(1.0f, 1.0f + __expf(-x));
}
__device__ __forceinline__ float tanhf_fast(float x) {
    return 1.0f - __fdividef(2.0f, __expf(2.0f * x) + 1.0f);
}

// ---------------------------------------------------------------------------
// Init: reset slot table (deterministic graph replays)
// ---------------------------------------------------------------------------
__global__ void init_kernel() {
    int n = (TT + 1) * NBLK;
    for (int i = blockIdx.x * blockDim.x + threadIdx.x; i < n;
         i += gridDim.x * blockDim.x)
        g_slots[i] = (i < NBLK) ? SOS_BIT : SENT;   // step 0 pre-released with SOS
}

// ---------------------------------------------------------------------------
// Encoder layer 0: V=29 -> H=64. 128 blocks x 512 threads (R11-proven).
// ---------------------------------------------------------------------------
__global__ __launch_bounds__(512, 1) void enc0_kernel(
    const float* __restrict__ x_seq,
    const float* __restrict__ Wih, const float* __restrict__ Whh,
    const float* __restrict__ bih, const float* __restrict__ bhh)
{
    __shared__ __align__(16) float xs[2][RR][32];
    __shared__ __align__(16) float hs[RR][HH];
    __shared__ float gs[RR][GG];

    const int tid  = threadIdx.x;
    const int g    = tid >> 1;
    const int half = tid & 1;
    const int kx0  = half * 16;
    const int kh0  = half * 32;
    const int r0   = blockIdx.x * RR;

    u64 wx[8], wh[16];
#pragma unroll
    for (int q = 0; q < 8; q++) {
        int k = kx0 + 2 * q;
        float a = (k < VV)     ? Wih[g * VV + k]     : 0.0f;
        float b = (k + 1 < VV) ? Wih[g * VV + k + 1] : 0.0f;
        wx[q] = pk2(a, b);
    }
#pragma unroll
    for (int q = 0; q < 16; q++)
        wh[q] = pk2(Whh[g * HH + kh0 + 2 * q], Whh[g * HH + kh0 + 2 * q + 1]);
    const float bias = half ? 0.0f : (bih[g] + bhh[g]);

    if (tid < 256) hs[tid >> 6][tid & 63] = 0.0f;
    if (tid < 2 * RR * 3) {
        int b = tid / (RR * 3), r = (tid / 3) % RR, k = VV + tid % 3;
        xs[b][r][k] = 0.0f;
    }
    if (tid < RR * VV) {
        int row = tid / VV, v = tid % VV;
        xs[0][row][v] = x_seq[((size_t)0 * BB + r0 + row) * VV + v];
    }
    float c = 0.0f;
    __syncthreads();

    int cur = 0;
    for (int step = 0; step < TT; step++) {
#pragma unroll
        for (int row = 0; row < RR; row++) {
            const u64* xp = (const u64*)&xs[cur][row][kx0];
            const u64* hp = (const u64*)&hs[row][kh0];
            u64 a0 = 0ull, a1 = 0ull;
#pragma unroll
            for (int q = 0; q < 8; q += 2) {
                a0 = ffma2(wx[q],     xp[q],     a0);
                a1 = ffma2(wx[q + 1], xp[q + 1], a1);
            }
#pragma unroll
            for (int q = 0; q < 16; q += 2) {
                a0 = ffma2(wh[q],     hp[q],     a0);
                a1 = ffma2(wh[q + 1], hp[q + 1], a1);
            }
            float s = f2sum(fadd2(a0, a1)) + bias;
            s += __shfl_xor_sync(0xffffffffu, s, 1);
            if (!half) gs[row][g] = s;
        }
        if (step + 1 < TT && tid < RR * VV) {
            int row = tid / VV, v = tid % VV;
            xs[cur ^ 1][row][v] = x_seq[((size_t)(step + 1) * BB + r0 + row) * VV + v];
        }
        __syncthreads();

        if (tid < 256) {
            int row = tid >> 6, j = tid & 63;
            float gi = gs[row][j];
            float gf = gs[row][64 + j];
            float gc = gs[row][128 + j];
            float go = gs[row][192 + j];
            c = sigf(gf) * c + sigf(gi) * tanhf_fast(gc);
            float h = sigf(go) * tanhf_fast(c);
            hs[row][j] = h;
            g_y1[((size_t)step * BB + r0 + row) * HH + j] = h;
        }
        __syncthreads();
        cur ^= 1;
    }
}

// ---------------------------------------------------------------------------
// Encoder layer 1: H=64 -> H=64. Same skeleton, input from g_y1.
// ---------------------------------------------------------------------------
__global__ __launch_bounds__(512, 1) void enc1_kernel(
    const float* __restrict__ Wih, const float* __restrict__ Whh,
    const float* __restrict__ bih, const float* __restrict__ bhh)
{
    __shared__ __align__(16) float ys[2][RR * HH];
    __shared__ __align__(16) float hs[RR][HH];
    __shared__ float gs[RR][GG];

    const int tid  = threadIdx.x;
    const int g    = tid >> 1;
    const int half = tid & 1;
    const int kh0  = half * 32;
    const int r0   = blockIdx.x * RR;

    u64 wx[16], wh[16];
#pragma unroll
    for (int q = 0; q < 16; q++) {
        wx[q] = pk2(Wih[g * HH + kh0 + 2 * q], Wih[g * HH + kh0 + 2 * q + 1]);
        wh[q] = pk2(Whh[g * HH + kh0 + 2 * q], Whh[g * HH + kh0 + 2 * q + 1]);
    }
    const float bias = half ? 0.0f : (bih[g] + bhh[g]);

    if (tid < 256) hs[tid >> 6][tid & 63] = 0.0f;
    if (tid < 64)
        ((float4*)ys[0])[tid] = ((const float4*)(g_y1 + (size_t)r0 * HH))[tid];
    float c = 0.0f;
    __syncthreads();

    int cur = 0;
    for (int step = 0; step < TT; step++) {
#pragma unroll
        for (int row = 0; row < RR; row++) {
            const u64* xp = (const u64*)&ys[cur][row * HH + kh0];
            const u64* hp = (const u64*)&hs[row][kh0];
            u64 a0 = 0ull, a1 = 0ull;
#pragma unroll
            for (int q = 0; q < 16; q += 2) {
                a0 = ffma2(wx[q],     xp[q],     a0);
                a1 = ffma2(wx[q + 1], xp[q + 1], a1);
            }
#pragma unroll
            for (int q = 0; q < 16; q += 2) {
                a0 = ffma2(wh[q],     hp[q],     a0);
                a1 = ffma2(wh[q + 1], hp[q + 1], a1);
            }
            float s = f2sum(fadd2(a0, a1)) + bias;
            s += __shfl_xor_sync(0xffffffffu, s, 1);
            if (!half) gs[row][g] = s;
        }
        if (step + 1 < TT && tid < 64)
            ((float4*)ys[cur ^ 1])[tid] =
                ((const float4*)(g_y1 + (size_t)(step + 1) * BB * HH + (size_t)r0 * HH))[tid];
        __syncthreads();

        if (tid < 256) {
            int row = tid >> 6, j = tid & 63;
            float gi = gs[row][j];
            float gf = gs[row][64 + j];
            float gc = gs[row][128 + j];
            float go = gs[row][192 + j];
            c = sigf(gf) * c + sigf(gi) * tanhf_fast(gc);
            float h = sigf(go) * tanhf_fast(c);
            hs[row][j] = h;
            if (step == TT - 1) {
                g_h1[(size_t)r0 * HH + tid] = h;
                g_c1[(size_t)r0 * HH + tid] = c;
            }
        }
        __syncthreads();
        cur ^= 1;
    }
}

// ---------------------------------------------------------------------------
// Decoder: persistent, 128 blocks x 512 threads (R11 compute, NEW sync).
// Sync: each block publishes its 4-row argmax bits to g_slots[step+1][bid]
// (release store, 128 distinct addresses -> parallel fan-in). Warp 0 polls all
// 128 slots of the current step (sentinel-guarded volatile v4 loads),
// OR-reduces, broadcasts via smem. No same-address atomics anywhere.
// ---------------------------------------------------------------------------
__global__ __launch_bounds__(512, 1) void dec_kernel(
    const float* __restrict__ d1_Wih, const float* __restrict__ d1_Whh,
    const float* __restrict__ d1_bih, const float* __restrict__ d1_bhh,
    const float* __restrict__ d2_Wih, const float* __restrict__ d2_Whh,
    const float* __restrict__ d2_bih, const float* __restrict__ d2_bhh,
    const float* __restrict__ cls_W, const float* __restrict__ cls_b,
    float* __restrict__ out)
{
    __shared__ float wih1T[VV * GG];                 // [j][g] letc table
    __shared__ __align__(16) u64 clsP[32 * 32];      // [kpair][v] packed cls weights
    __shared__ __align__(16) float h1s[RR * HH];
    __shared__ __align__(16) float h2s[RR * HH];
    __shared__ float g1s[RR * GG];
    __shared__ float g2s[RR * GG];
    __shared__ __align__(16) float ps[RR * 32];
    __shared__ float clsb[32];
    __shared__ unsigned smaskS;

    const int tid  = threadIdx.x;
    const int g    = tid >> 1;
    const int half = tid & 1;
    const int ko   = half * 32;
    const int r0   = blockIdx.x * RR;

    u64 whh1[16], wih2[16], whh2[16];
#pragma unroll
    for (int q = 0; q < 16; q++) {
        whh1[q] = pk2(d1_Whh[g * HH + ko + 2 * q], d1_Whh[g * HH + ko + 2 * q + 1]);
        wih2[q] = pk2(d2_Wih[g * HH + ko + 2 * q], d2_Wih[g * HH + ko + 2 * q + 1]);
        whh2[q] = pk2(d2_Whh[g * HH + ko + 2 * q], d2_Whh[g * HH + ko + 2 * q + 1]);
    }
    const float bias1 = half ? 0.0f : (d1_bih[g] + d1_bhh[g]);
    const float bias2 = half ? 0.0f : (d2_bih[g] + d2_bhh[g]);

    for (int i = tid; i < VV * GG; i += 512)
        wih1T[(i % VV) * GG + (i / VV)] = d1_Wih[i];
    for (int i = tid; i < VV * 32; i += 512) {
        int v = i >> 5, kk = i & 31;
        clsP[kk * 32 + v] = pk2(cls_W[v * HH + 2 * kk], cls_W[v * HH + 2 * kk + 1]);
    }
    if (tid < VV) clsb[tid] = cls_b[tid];
    if (tid < RR * 3) ps[(tid / 3) * 32 + VV + tid % 3] = -CUDART_INF_F;

    float c;
    if (tid < 256) {
        h1s[tid] = g_h1[(size_t)r0 * HH + tid];
        c        = g_c1[(size_t)r0 * HH + tid];
        h2s[tid] = 0.0f;
    } else {
        c = 0.0f;
    }
    __syncthreads();

    // letc j-range split across the pair (folds into the gate shfl-reduce)
    const int j0 = half ? 15 : 0;
    const int j1 = half ? VV : 15;

    for (int step = 0; step < TT; step++) {
        // ---- pre-phase: mask-independent h2 * Whh2 dot (hides the poll) ----
        u64 acc2[RR];
#pragma unroll
        for (int row = 0; row < RR; row++) {
            const u64* hp = (const u64*)&h2s[row * HH + ko];
            u64 a0 = 0ull, a1 = 0ull;
#pragma unroll
            for (int q = 0; q < 16; q += 2) {
                a0 = ffma2(whh2[q],     hp[q],     a0);
                a1 = ffma2(whh2[q + 1], hp[q + 1], a1);
            }
            acc2[row] = fadd2(a0, a1);
        }

        // ---- warp 0 polls this step's 128 slots; others wait at the bar ----
        if (tid < 32) {
            const unsigned* base = g_slots + (size_t)step * NBLK + tid * 4;
            unsigned m;
            for (;;) {
                uint4 v = ld_vol4(base);
                unsigned bad = (v.x == SENT) | (v.y == SENT) |
                               (v.z == SENT) | (v.w == SENT);
                if (!__any_sync(0xffffffffu, bad)) {
                    m = v.x | v.y | v.z | v.w;
                    break;
                }
            }
            m |= __shfl_xor_sync(0xffffffffu, m, 1);
            m |= __shfl_xor_sync(0xffffffffu, m, 2);
            m |= __shfl_xor_sync(0xffffffffu, m, 4);
            m |= __shfl_xor_sync(0xffffffffu, m, 8);
            m |= __shfl_xor_sync(0xffffffffu, m, 16);
            if (tid == 0) smaskS = m;
        }
        __syncthreads();                       // A: mask visible to all
        const unsigned mask = smaskS;

        // ---- cell1 gates: (letc-half + bias) + h1 * Whh1 (pair k-split) ----
        float ls = bias1;
        for (int j = j0; j < j1; j++)
            if ((mask >> j) & 1u) ls += wih1T[j * GG + g];
#pragma unroll
        for (int row = 0; row < RR; row++) {
            const u64* hp = (const u64*)&h1s[row * HH + ko];
            u64 a0 = 0ull, a1 = 0ull;
#pragma unroll
            for (int q = 0; q < 16; q += 2) {
                a0 = ffma2(whh1[q],     hp[q],     a0);
                a1 = ffma2(whh1[q + 1], hp[q + 1], a1);
            }
            float s = f2sum(fadd2(a0, a1)) + ls;
            s += __shfl_xor_sync(0xffffffffu, s, 1);
            if (!half) g1s[row * GG + g] = s;
        }
        __syncthreads();

        // ---- cell1 pointwise (tid<256 owns c1) ----
        if (tid < 256) {
            int row = tid >> 6, j = tid & 63;
            float gi = g1s[row * GG + j];
            float gf = g1s[row * GG + 64 + j];
            float gc = g1s[row * GG + 128 + j];
            float go = g1s[row * GG + 192 + j];
            c = sigf(gf) * c + sigf(gi) * tanhf_fast(gc);
            h1s[tid] = sigf(go) * tanhf_fast(c);
        }
        __syncthreads();

        // ---- cell2 gates: h1_new * Wih2 + precomputed h2-dot ----
#pragma unroll
        for (int row = 0; row < RR; row++) {
            const u64* hp = (const u64*)&h1s[row * HH + ko];
            u64 a = acc2[row];
#pragma unroll
            for (int q = 0; q < 16; q++)
                a = ffma2(wih2[q], hp[q], a);
            float s = f2sum(a) + bias2;
            s += __shfl_xor_sync(0xffffffffu, s, 1);
            if (!half) g2s[row * GG + g] = s;
        }
        __syncthreads();

        // ---- cell2 pointwise (tid>=256 owns c2) ----
        if (tid >= 256) {
            int t2 = tid - 256;
            int row = t2 >> 6, j = t2 & 63;
            float gi = g2s[row * GG + j];
            float gf = g2s[row * GG + 64 + j];
            float gc = g2s[row * GG + 128 + j];
            float go = g2s[row * GG + 192 + j];
            c = sigf(gf) * c + sigf(gi) * tanhf_fast(gc);
            h2s[t2] = sigf(go) * tanhf_fast(c);
        }
        __syncthreads();

        // ---- classifier (tid<256, pair k-split over 116 (row,v) pairs) ----
        if (tid < 256) {
            int p = tid >> 1;
            bool valid = p < RR * VV;
            int pc = valid ? p : 0;
            int row = pc / VV, v = pc - row * VV;
            const u64* hp = (const u64*)&h2s[row * HH] + half * 16;
            u64 a = 0ull;
#pragma unroll
            for (int q = 0; q < 16; q++)
                a = ffma2(clsP[(half * 16 + q) * 32 + v], hp[q], a);
            float s = f2sum(a) + (half ? 0.0f : clsb[v]);
            s += __shfl_xor_sync(0xffffffffu, s, 1);
            if (valid && !half) {
                ps[row * 32 + v] = s;
                out[((size_t)step * BB + r0 + row) * VV + v] = s;
            }
        }
        __syncthreads();

        // ---- argmax (warp 0) + publish this block's slot for step+1 ----
        if (tid < 32) {
            int row = tid >> 3, sl = tid & 7;
            float4 vv = *(const float4*)&ps[row * 32 + sl * 4];
            float best = vv.x; int bi = sl * 4;
            if (vv.y > best) { best = vv.y; bi = sl * 4 + 1; }
            if (vv.z > best) { best = vv.z; bi = sl * 4 + 2; }
            if (vv.w > best) { best = vv.w; bi = sl * 4 + 3; }
#pragma unroll
            for (int off = 1; off <= 4; off <<= 1) {
                float ob = __shfl_xor_sync(0xffffffffu, best, off);
                int   oi = __shfl_xor_sync(0xffffffffu, bi,   off);
                if (ob > best || (ob == best && oi < bi)) { best = ob; bi = oi; }
            }
            unsigned bits = (sl == 0) ? (1u << bi) : 0u;
            bits |= __shfl_xor_sync(0xffffffffu, bits, 8);
            bits |= __shfl_xor_sync(0xffffffffu, bits, 16);
            if (tid == 0)
                st_rel(&g_slots[(size_t)(step + 1) * NBLK + blockIdx.x], bits);
        }
        // no trailing sync: next pre-phase only READS h2s (stable since pw2 bar)
    }
}

// ---------------------------------------------------------------------------
// Launch
// ---------------------------------------------------------------------------
extern "C" void kernel_launch(void* const* d_in, const int* in_sizes, int n_in,
                              void* d_out, int out_size)
{
    const float* input_seq = (const float*)d_in[0];
    const float* enc_Wih0  = (const float*)d_in[1];
    const float* enc_Whh0  = (const float*)d_in[2];
    const float* enc_bih0  = (const float*)d_in[3];
    const float* enc_bhh0  = (const float*)d_in[4];
    const float* enc_Wih1  = (const float*)d_in[5];
    const float* enc_Whh1  = (const float*)d_in[6];
    const float* enc_bih1  = (const float*)d_in[7];
    const float* enc_bhh1  = (const float*)d_in[8];
    const float* d1_Wih    = (const float*)d_in[9];
    const float* d1_Whh    = (const float*)d_in[10];
    const float* d1_bih    = (const float*)d_in[11];
    const float* d1_bhh    = (const float*)d_in[12];
    const float* d2_Wih    = (const float*)d_in[13];
    const float* d2_Whh    = (const float*)d_in[14];
    const float* d2_bih    = (const float*)d_in[15];
    const float* d2_bhh    = (const float*)d_in[16];
    const float* cls_W     = (const float*)d_in[17];
    const float* cls_b     = (const float*)d_in[18];
    float* out = (float*)d_out;

    init_kernel<<<64, 512>>>();
    enc0_kernel<<<NBLK, 512>>>(input_seq, enc_Wih0, enc_Whh0, enc_bih0, enc_bhh0);
    enc1_kernel<<<NBLK, 512>>>(enc_Wih1, enc_Whh1, enc_bih1, enc_bhh1);
    dec_kernel<<<NBLK, 512>>>(d1_Wih, d1_Whh, d1_bih, d1_bhh,
                              d2_Wih, d2_Whh, d2_bih, d2_bhh,
                              cls_W, cls_b, out);
}

// round 14
// speedup vs baseline: 1.1965x; 1.0174x over previous
#include <cuda_runtime.h>
#include <cstdint>
#include <cstddef>
#include <math_constants.h>

#define TT 1024
#define BB 512
#define VV 29
#define HH 64
#define GG 256          // 4*H
#define RR 4            // batch rows per block
#define NBLK 128        // 512 / 4
#define SOS_BIT (1u << 27)
#define SENT 0xFFFFFFFFu   // sentinel: valid masks are <= 0x1FFFFFFF

// ---------------------------------------------------------------------------
// Device scratch
// ---------------------------------------------------------------------------
__device__ float g_y1[(size_t)TT * BB * HH];   // encoder layer0 output (134 MB)
__device__ float g_h1[BB * HH];
__device__ float g_c1[BB * HH];
// per-(step, block) published argmax-bit slots; sentinel = not yet written
__device__ __align__(16) unsigned g_slots[(TT + 1) * NBLK];

typedef unsigned long long u64;

// ---------------------------------------------------------------------------
// f32x2 packed-FMA helpers
// ---------------------------------------------------------------------------
__device__ __forceinline__ u64 ffma2(u64 a, u64 b, u64 c) {
    u64 d; asm("fma.rn.f32x2 %0, %1, %2, %3;" : "=l"(d) : "l"(a), "l"(b), "l"(c));
    return d;
}
__device__ __forceinline__ u64 fadd2(u64 a, u64 b) {
    u64 d; asm("add.rn.f32x2 %0, %1, %2;" : "=l"(d) : "l"(a), "l"(b));
    return d;
}
__device__ __forceinline__ u64 pk2(float lo, float hi) {
    u64 d; asm("mov.b64 %0, {%1, %2};" : "=l"(d) : "f"(lo), "f"(hi));
    return d;
}
__device__ __forceinline__ float f2sum(u64 a) {
    float lo, hi; asm("mov.b64 {%0, %1}, %2;" : "=f"(lo), "=f"(hi) : "l"(a));
    return lo + hi;
}
__device__ __forceinline__ uint4 ld_vol4(const unsigned* p) {
    uint4 v;
    asm volatile("ld.volatile.global.v4.u32 {%0,%1,%2,%3}, [%4];"
                 : "=r"(v.x), "=r"(v.y), "=r"(v.z), "=r"(v.w) : "l"(p) : "memory");
    return v;
}
__device__ __forceinline__ void st_rel(unsigned* p, unsigned v) {
    asm volatile("st.release.gpu.global.u32 [%0], %1;" :: "l"(p), "r"(v) : "memory");
}
// Fast transcendentals (single-MUFU forms, limit-correct, rel err ~1e-6)
__device__ __forceinline__ float sigf(float x) {
    return __fdividef(1.0f, 1.0f + __expf(-x));
}
__device__ __forceinline__ float tanhf_fast(float x) {
    return 1.0f - __fdividef(2.0f, __expf(2.0f * x) + 1.0f);
}

// ---------------------------------------------------------------------------
// Init: reset slot table (deterministic graph replays)
// ---------------------------------------------------------------------------
__global__ void init_kernel() {
    int n = (TT + 1) * NBLK;
    for (int i = blockIdx.x * blockDim.x + threadIdx.x; i < n;
         i += gridDim.x * blockDim.x)
        g_slots[i] = (i < NBLK) ? SOS_BIT : SENT;   // step 0 pre-released with SOS
}

// ---------------------------------------------------------------------------
// Encoder layer 0: V=29 -> H=64. 128 blocks x 512 threads (R11-proven).
// ---------------------------------------------------------------------------
__global__ __launch_bounds__(512, 1) void enc0_kernel(
    const float* __restrict__ x_seq,
    const float* __restrict__ Wih, const float* __restrict__ Whh,
    const float* __restrict__ bih, const float* __restrict__ bhh)
{
    __shared__ __align__(16) float xs[2][RR][32];
    __shared__ __align__(16) float hs[RR][HH];
    __shared__ float gs[RR][GG];

    const int tid  = threadIdx.x;
    const int g    = tid >> 1;
    const int half = tid & 1;
    const int kx0  = half * 16;
    const int kh0  = half * 32;
    const int r0   = blockIdx.x * RR;

    u64 wx[8], wh[16];
#pragma unroll
    for (int q = 0; q < 8; q++) {
        int k = kx0 + 2 * q;
        float a = (k < VV)     ? Wih[g * VV + k]     : 0.0f;
        float b = (k + 1 < VV) ? Wih[g * VV + k + 1] : 0.0f;
        wx[q] = pk2(a, b);
    }
#pragma unroll
    for (int q = 0; q < 16; q++)
        wh[q] = pk2(Whh[g * HH + kh0 + 2 * q], Whh[g * HH + kh0 + 2 * q + 1]);
    const float bias = half ? 0.0f : (bih[g] + bhh[g]);

    if (tid < 256) hs[tid >> 6][tid & 63] = 0.0f;
    if (tid < 2 * RR * 3) {
        int b = tid / (RR * 3), r = (tid / 3) % RR, k = VV + tid % 3;
        xs[b][r][k] = 0.0f;
    }
    if (tid < RR * VV) {
        int row = tid / VV, v = tid % VV;
        xs[0][row][v] = x_seq[((size_t)0 * BB + r0 + row) * VV + v];
    }
    float c = 0.0f;
    __syncthreads();

    int cur = 0;
    for (int step = 0; step < TT; step++) {
#pragma unroll
        for (int row = 0; row < RR; row++) {
            const u64* xp = (const u64*)&xs[cur][row][kx0];
            const u64* hp = (const u64*)&hs[row][kh0];
            u64 a0 = 0ull, a1 = 0ull;
#pragma unroll
            for (int q = 0; q < 8; q += 2) {
                a0 = ffma2(wx[q],     xp[q],     a0);
                a1 = ffma2(wx[q + 1], xp[q + 1], a1);
            }
#pragma unroll
            for (int q = 0; q < 16; q += 2) {
                a0 = ffma2(wh[q],     hp[q],     a0);
                a1 = ffma2(wh[q + 1], hp[q + 1], a1);
            }
            float s = f2sum(fadd2(a0, a1)) + bias;
            s += __shfl_xor_sync(0xffffffffu, s, 1);
            if (!half) gs[row][g] = s;
        }
        if (step + 1 < TT && tid < RR * VV) {
            int row = tid / VV, v = tid % VV;
            xs[cur ^ 1][row][v] = x_seq[((size_t)(step + 1) * BB + r0 + row) * VV + v];
        }
        __syncthreads();

        if (tid < 256) {
            int row = tid >> 6, j = tid & 63;
            float gi = gs[row][j];
            float gf = gs[row][64 + j];
            float gc = gs[row][128 + j];
            float go = gs[row][192 + j];
            c = sigf(gf) * c + sigf(gi) * tanhf_fast(gc);
            float h = sigf(go) * tanhf_fast(c);
            hs[row][j] = h;
            g_y1[((size_t)step * BB + r0 + row) * HH + j] = h;
        }
        __syncthreads();
        cur ^= 1;
    }
}

// ---------------------------------------------------------------------------
// Encoder layer 1: H=64 -> H=64. Same skeleton, input from g_y1.
// ---------------------------------------------------------------------------
__global__ __launch_bounds__(512, 1) void enc1_kernel(
    const float* __restrict__ Wih, const float* __restrict__ Whh,
    const float* __restrict__ bih, const float* __restrict__ bhh)
{
    __shared__ __align__(16) float ys[2][RR * HH];
    __shared__ __align__(16) float hs[RR][HH];
    __shared__ float gs[RR][GG];

    const int tid  = threadIdx.x;
    const int g    = tid >> 1;
    const int half = tid & 1;
    const int kh0  = half * 32;
    const int r0   = blockIdx.x * RR;

    u64 wx[16], wh[16];
#pragma unroll
    for (int q = 0; q < 16; q++) {
        wx[q] = pk2(Wih[g * HH + kh0 + 2 * q], Wih[g * HH + kh0 + 2 * q + 1]);
        wh[q] = pk2(Whh[g * HH + kh0 + 2 * q], Whh[g * HH + kh0 + 2 * q + 1]);
    }
    const float bias = half ? 0.0f : (bih[g] + bhh[g]);

    if (tid < 256) hs[tid >> 6][tid & 63] = 0.0f;
    if (tid < 64)
        ((float4*)ys[0])[tid] = ((const float4*)(g_y1 + (size_t)r0 * HH))[tid];
    float c = 0.0f;
    __syncthreads();

    int cur = 0;
    for (int step = 0; step < TT; step++) {
#pragma unroll
        for (int row = 0; row < RR; row++) {
            const u64* xp = (const u64*)&ys[cur][row * HH + kh0];
            const u64* hp = (const u64*)&hs[row][kh0];
            u64 a0 = 0ull, a1 = 0ull;
#pragma unroll
            for (int q = 0; q < 16; q += 2) {
                a0 = ffma2(wx[q],     xp[q],     a0);
                a1 = ffma2(wx[q + 1], xp[q + 1], a1);
            }
#pragma unroll
            for (int q = 0; q < 16; q += 2) {
                a0 = ffma2(wh[q],     hp[q],     a0);
                a1 = ffma2(wh[q + 1], hp[q + 1], a1);
            }
            float s = f2sum(fadd2(a0, a1)) + bias;
            s += __shfl_xor_sync(0xffffffffu, s, 1);
            if (!half) gs[row][g] = s;
        }
        if (step + 1 < TT && tid < 64)
            ((float4*)ys[cur ^ 1])[tid] =
                ((const float4*)(g_y1 + (size_t)(step + 1) * BB * HH + (size_t)r0 * HH))[tid];
        __syncthreads();

        if (tid < 256) {
            int row = tid >> 6, j = tid & 63;
            float gi = gs[row][j];
            float gf = gs[row][64 + j];
            float gc = gs[row][128 + j];
            float go = gs[row][192 + j];
            c = sigf(gf) * c + sigf(gi) * tanhf_fast(gc);
            float h = sigf(go) * tanhf_fast(c);
            hs[row][j] = h;
            if (step == TT - 1) {
                g_h1[(size_t)r0 * HH + tid] = h;
                g_c1[(size_t)r0 * HH + tid] = c;
            }
        }
        __syncthreads();
        cur ^= 1;
    }
}

// ---------------------------------------------------------------------------
// Decoder: persistent, 128 blocks x 512 threads.
// NEW this round: the FULL mask-independent cell1 dot (bias1 + h1*Whh1) is
// pair-reduced and stored to g1s BEFORE the poll (alongside acc2 = h2*Whh2),
// so the post-mask critical chain shrinks to: letc -> pw1 -> gates2 -> pw2 ->
// cls -> argmax. Sync remains R13's slot scheme (release store per block,
// warp-0 sentinel poll, no same-address atomics).
// ---------------------------------------------------------------------------
__global__ __launch_bounds__(512, 1) void dec_kernel(
    const float* __restrict__ d1_Wih, const float* __restrict__ d1_Whh,
    const float* __restrict__ d1_bih, const float* __restrict__ d1_bhh,
    const float* __restrict__ d2_Wih, const float* __restrict__ d2_Whh,
    const float* __restrict__ d2_bih, const float* __restrict__ d2_bhh,
    const float* __restrict__ cls_W, const float* __restrict__ cls_b,
    float* __restrict__ out)
{
    __shared__ float wih1T[VV * GG];                 // [j][g] letc table
    __shared__ __align__(16) u64 clsP[32 * 32];      // [kpair][v] packed cls weights
    __shared__ __align__(16) float h1s[RR * HH];
    __shared__ __align__(16) float h2s[RR * HH];
    __shared__ float g1s[RR * GG];
    __shared__ float g2s[RR * GG];
    __shared__ float letc[GG];
    __shared__ __align__(16) float ps[RR * 32];
    __shared__ float clsb[32];
    __shared__ unsigned smaskS;

    const int tid  = threadIdx.x;
    const int g    = tid >> 1;
    const int half = tid & 1;
    const int ko   = half * 32;
    const int r0   = blockIdx.x * RR;

    u64 whh1[16], wih2[16], whh2[16];
#pragma unroll
    for (int q = 0; q < 16; q++) {
        whh1[q] = pk2(d1_Whh[g * HH + ko + 2 * q], d1_Whh[g * HH + ko + 2 * q + 1]);
        wih2[q] = pk2(d2_Wih[g * HH + ko + 2 * q], d2_Wih[g * HH + ko + 2 * q + 1]);
        whh2[q] = pk2(d2_Whh[g * HH + ko + 2 * q], d2_Whh[g * HH + ko + 2 * q + 1]);
    }
    const float bias1 = half ? 0.0f : (d1_bih[g] + d1_bhh[g]);
    const float bias2 = half ? 0.0f : (d2_bih[g] + d2_bhh[g]);

    for (int i = tid; i < VV * GG; i += 512)
        wih1T[(i % VV) * GG + (i / VV)] = d1_Wih[i];
    for (int i = tid; i < VV * 32; i += 512) {
        int v = i >> 5, kk = i & 31;
        clsP[kk * 32 + v] = pk2(cls_W[v * HH + 2 * kk], cls_W[v * HH + 2 * kk + 1]);
    }
    if (tid < VV) clsb[tid] = cls_b[tid];
    if (tid < RR * 3) ps[(tid / 3) * 32 + VV + tid % 3] = -CUDART_INF_F;

    float c;
    if (tid < 256) {
        h1s[tid] = g_h1[(size_t)r0 * HH + tid];
        c        = g_c1[(size_t)r0 * HH + tid];
        h2s[tid] = 0.0f;
    } else {
        c = 0.0f;
    }
    __syncthreads();

    // letc j-range split across the pair
    const int j0 = half ? 15 : 0;
    const int j1 = half ? VV : 15;

    for (int step = 0; step < TT; step++) {
        // ---- pre-phase (mask-independent, overlaps the poll wait) ----
        // (a) cell1 pre-gates: bias1 + h1 * Whh1, pair-reduced into g1s
#pragma unroll
        for (int row = 0; row < RR; row++) {
            const u64* hp = (const u64*)&h1s[row * HH + ko];
            u64 a0 = 0ull, a1 = 0ull;
#pragma unroll
            for (int q = 0; q < 16; q += 2) {
                a0 = ffma2(whh1[q],     hp[q],     a0);
                a1 = ffma2(whh1[q + 1], hp[q + 1], a1);
            }
            float s = f2sum(fadd2(a0, a1)) + bias1;
            s += __shfl_xor_sync(0xffffffffu, s, 1);
            if (!half) g1s[row * GG + g] = s;
        }
        // (b) cell2 h2-dot kept in registers
        u64 acc2[RR];
#pragma unroll
        for (int row = 0; row < RR; row++) {
            const u64* hp = (const u64*)&h2s[row * HH + ko];
            u64 a0 = 0ull, a1 = 0ull;
#pragma unroll
            for (int q = 0; q < 16; q += 2) {
                a0 = ffma2(whh2[q],     hp[q],     a0);
                a1 = ffma2(whh2[q + 1], hp[q + 1], a1);
            }
            acc2[row] = fadd2(a0, a1);
        }

        // ---- warp 0 polls this step's 128 slots; others wait at the bar ----
        if (tid < 32) {
            const unsigned* base = g_slots + (size_t)step * NBLK + tid * 4;
            unsigned m;
            for (;;) {
                uint4 v = ld_vol4(base);
                unsigned bad = (v.x == SENT) | (v.y == SENT) |
                               (v.z == SENT) | (v.w == SENT);
                if (!__any_sync(0xffffffffu, bad)) {
                    m = v.x | v.y | v.z | v.w;
                    break;
                }
            }
            m |= __shfl_xor_sync(0xffffffffu, m, 1);
            m |= __shfl_xor_sync(0xffffffffu, m, 2);
            m |= __shfl_xor_sync(0xffffffffu, m, 4);
            m |= __shfl_xor_sync(0xffffffffu, m, 8);
            m |= __shfl_xor_sync(0xffffffffu, m, 16);
            if (tid == 0) smaskS = m;
        }
        __syncthreads();                       // A: mask + g1s visible
        const unsigned mask = smaskS;

        // ---- letc phase (skinny): pair j-split sums of wih1T columns ----
        {
            float ls = 0.0f;
            for (int j = j0; j < j1; j++)
                if ((mask >> j) & 1u) ls += wih1T[j * GG + g];
            ls += __shfl_xor_sync(0xffffffffu, ls, 1);
            if (!half) letc[g] = ls;
        }
        __syncthreads();                       // B: letc ready

        // ---- cell1 pointwise (tid<256 owns c1): g1s + letc ----
        if (tid < 256) {
            int row = tid >> 6, j = tid & 63;
            float gi = g1s[row * GG + j]       + letc[j];
            float gf = g1s[row * GG + 64 + j]  + letc[64 + j];
            float gc = g1s[row * GG + 128 + j] + letc[128 + j];
            float go = g1s[row * GG + 192 + j] + letc[192 + j];
            c = sigf(gf) * c + sigf(gi) * tanhf_fast(gc);
            h1s[tid] = sigf(go) * tanhf_fast(c);
        }
        __syncthreads();                       // C: h1 new

        // ---- cell2 gates: h1_new * Wih2 + precomputed h2-dot ----
#pragma unroll
        for (int row = 0; row < RR; row++) {
            const u64* hp = (const u64*)&h1s[row * HH + ko];
            u64 a = acc2[row];
#pragma unroll
            for (int q = 0; q < 16; q++)
                a = ffma2(wih2[q], hp[q], a);
            float s = f2sum(a) + bias2;
            s += __shfl_xor_sync(0xffffffffu, s, 1);
            if (!half) g2s[row * GG + g] = s;
        }
        __syncthreads();                       // D: g2 ready

        // ---- cell2 pointwise (tid>=256 owns c2) ----
        if (tid >= 256) {
            int t2 = tid - 256;
            int row = t2 >> 6, j = t2 & 63;
            float gi = g2s[row * GG + j];
            float gf = g2s[row * GG + 64 + j];
            float gc = g2s[row * GG + 128 + j];
            float go = g2s[row * GG + 192 + j];
            c = sigf(gf) * c + sigf(gi) * tanhf_fast(gc);
            h2s[t2] = sigf(go) * tanhf_fast(c);
        }
        __syncthreads();                       // E: h2 new

        // ---- classifier (tid<256, pair k-split over 116 (row,v) pairs) ----
        if (tid < 256) {
            int p = tid >> 1;
            bool valid = p < RR * VV;
            int pc = valid ? p : 0;
            int row = pc / VV, v = pc - row * VV;
            const u64* hp = (const u64*)&h2s[row * HH] + half * 16;
            u64 a = 0ull;
#pragma unroll
            for (int q = 0; q < 16; q++)
                a = ffma2(clsP[(half * 16 + q) * 32 + v], hp[q], a);
            float s = f2sum(a) + (half ? 0.0f : clsb[v]);
            s += __shfl_xor_sync(0xffffffffu, s, 1);
            if (valid && !half) {
                ps[row * 32 + v] = s;
                out[((size_t)step * BB + r0 + row) * VV + v] = s;
            }
        }
        __syncthreads();                       // F: ps ready

        // ---- argmax (warp 0) + publish this block's slot for step+1 ----
        if (tid < 32) {
            int row = tid >> 3, sl = tid & 7;
            float4 vv = *(const float4*)&ps[row * 32 + sl * 4];
            float best = vv.x; int bi = sl * 4;
            if (vv.y > best) { best = vv.y; bi = sl * 4 + 1; }
            if (vv.z > best) { best = vv.z; bi = sl * 4 + 2; }
            if (vv.w > best) { best = vv.w; bi = sl * 4 + 3; }
#pragma unroll
            for (int off = 1; off <= 4; off <<= 1) {
                float ob = __shfl_xor_sync(0xffffffffu, best, off);
                int   oi = __shfl_xor_sync(0xffffffffu, bi,   off);
                if (ob > best || (ob == best && oi < bi)) { best = ob; bi = oi; }
            }
            unsigned bits = (sl == 0) ? (1u << bi) : 0u;
            bits |= __shfl_xor_sync(0xffffffffu, bits, 8);
            bits |= __shfl_xor_sync(0xffffffffu, bits, 16);
            if (tid == 0)
                st_rel(&g_slots[(size_t)(step + 1) * NBLK + blockIdx.x], bits);
        }
        // no trailing sync: next pre-phase only READS h1s/h2s (stable since
        // bars C/E); g1s rewrite happens after all readers passed bar C.
    }
}

// ---------------------------------------------------------------------------
// Launch
// ---------------------------------------------------------------------------
extern "C" void kernel_launch(void* const* d_in, const int* in_sizes, int n_in,
                              void* d_out, int out_size)
{
    const float* input_seq = (const float*)d_in[0];
    const float* enc_Wih0  = (const float*)d_in[1];
    const float* enc_Whh0  = (const float*)d_in[2];
    const float* enc_bih0  = (const float*)d_in[3];
    const float* enc_bhh0  = (const float*)d_in[4];
    const float* enc_Wih1  = (const float*)d_in[5];
    const float* enc_Whh1  = (const float*)d_in[6];
    const float* enc_bih1  = (const float*)d_in[7];
    const float* enc_bhh1  = (const float*)d_in[8];
    const float* d1_Wih    = (const float*)d_in[9];
    const float* d1_Whh    = (const float*)d_in[10];
    const float* d1_bih    = (const float*)d_in[11];
    const float* d1_bhh    = (const float*)d_in[12];
    const float* d2_Wih    = (const float*)d_in[13];
    const float* d2_Whh    = (const float*)d_in[14];
    const float* d2_bih    = (const float*)d_in[15];
    const float* d2_bhh    = (const float*)d_in[16];
    const float* cls_W     = (const float*)d_in[17];
    const float* cls_b     = (const float*)d_in[18];
    float* out = (float*)d_out;

    init_kernel<<<64, 512>>>();
    enc0_kernel<<<NBLK, 512>>>(input_seq, enc_Wih0, enc_Whh0, enc_bih0, enc_bhh0);
    enc1_kernel<<<NBLK, 512>>>(enc_Wih1, enc_Whh1, enc_bih1, enc_bhh1);
    dec_kernel<<<NBLK, 512>>>(d1_Wih, d1_Whh, d1_bih, d1_bhh,
                              d2_Wih, d2_Whh, d2_bih, d2_bhh,
                              cls_W, cls_b, out);
}

// round 17
// speedup vs baseline: 1.2579x; 1.0513x over previous
#include <cuda_runtime.h>
#include <cstdint>
#include <cstddef>
#include <math_constants.h>

#define TT 1024
#define BB 512
#define VV 29
#define HH 64
#define GG 256          // 4*H
#define RR 4            // batch rows per block
#define NBLK 128        // 512 / 4
#define SOS_BIT (1u << 27)
#define SENT 0xFFFFFFFFu   // sentinel: valid masks are <= 0x1FFFFFFF

// ---------------------------------------------------------------------------
// Device scratch
// ---------------------------------------------------------------------------
__device__ float g_y1[(size_t)TT * BB * HH];   // encoder layer0 output (134 MB)
__device__ float g_h1[BB * HH];
__device__ float g_c1[BB * HH];
// per-(step, block) published argmax-bit slots; sentinel = not yet written
__device__ __align__(16) unsigned g_slots[(TT + 1) * NBLK];

typedef unsigned long long u64;

// ---------------------------------------------------------------------------
// f32x2 packed-FMA helpers
// ---------------------------------------------------------------------------
__device__ __forceinline__ u64 ffma2(u64 a, u64 b, u64 c) {
    u64 d; asm("fma.rn.f32x2 %0, %1, %2, %3;" : "=l"(d) : "l"(a), "l"(b), "l"(c));
    return d;
}
__device__ __forceinline__ u64 fadd2(u64 a, u64 b) {
    u64 d; asm("add.rn.f32x2 %0, %1, %2;" : "=l"(d) : "l"(a), "l"(b));
    return d;
}
__device__ __forceinline__ u64 pk2(float lo, float hi) {
    u64 d; asm("mov.b64 %0, {%1, %2};" : "=l"(d) : "f"(lo), "f"(hi));
    return d;
}
__device__ __forceinline__ float f2sum(u64 a) {
    float lo, hi; asm("mov.b64 {%0, %1}, %2;" : "=f"(lo), "=f"(hi) : "l"(a));
    return lo + hi;
}
__device__ __forceinline__ uint4 ld_vol4(const unsigned* p) {
    uint4 v;
    asm volatile("ld.volatile.global.v4.u32 {%0,%1,%2,%3}, [%4];"
                 : "=r"(v.x), "=r"(v.y), "=r"(v.z), "=r"(v.w) : "l"(p) : "memory");
    return v;
}
__device__ __forceinline__ void st_rel(unsigned* p, unsigned v) {
    asm volatile("st.release.gpu.global.u32 [%0], %1;" :: "l"(p), "r"(v) : "memory");
}
// Fast transcendentals (single-MUFU forms, limit-correct, rel err ~1e-6)
__device__ __forceinline__ float sigf(float x) {
    return __fdividef(1.0f, 1.0f + __expf(-x));
}
__device__ __forceinline__ float tanhf_fast(float x) {
    return 1.0f - __fdividef(2.0f, __expf(2.0f * x) + 1.0f);
}

// ---------------------------------------------------------------------------
// Init: reset slot table (deterministic graph replays)
// ---------------------------------------------------------------------------
__global__ void init_kernel() {
    int n = (TT + 1) * NBLK;
    for (int i = blockIdx.x * blockDim.x + threadIdx.x; i < n;
         i += gridDim.x * blockDim.x)
        g_slots[i] = (i < NBLK) ? SOS_BIT : SENT;   // step 0 pre-released with SOS
}

// ---------------------------------------------------------------------------
// Encoder layer 0: V=29 -> H=64. 128 blocks x 512 threads.
// NEW: next-step x prefetched into REGISTERS at the top of the iteration so
// the DRAM latency overlaps the gate phase instead of extending the barrier.
// ---------------------------------------------------------------------------
__global__ __launch_bounds__(512, 1) void enc0_kernel(
    const float* __restrict__ x_seq,
    const float* __restrict__ Wih, const float* __restrict__ Whh,
    const float* __restrict__ bih, const float* __restrict__ bhh)
{
    __shared__ __align__(16) float xs[2][RR][32];
    __shared__ __align__(16) float hs[RR][HH];
    __shared__ float gs[RR][GG];

    const int tid  = threadIdx.x;
    const int g    = tid >> 1;
    const int half = tid & 1;
    const int kx0  = half * 16;
    const int kh0  = half * 32;
    const int r0   = blockIdx.x * RR;
    const bool ldr = tid < RR * VV;           // prefetch-loader thread
    const int lrow = ldr ? tid / VV : 0;
    const int lv   = ldr ? tid % VV : 0;

    u64 wx[8], wh[16];
#pragma unroll
    for (int q = 0; q < 8; q++) {
        int k = kx0 + 2 * q;
        float a = (k < VV)     ? Wih[g * VV + k]     : 0.0f;
        float b = (k + 1 < VV) ? Wih[g * VV + k + 1] : 0.0f;
        wx[q] = pk2(a, b);
    }
#pragma unroll
    for (int q = 0; q < 16; q++)
        wh[q] = pk2(Whh[g * HH + kh0 + 2 * q], Whh[g * HH + kh0 + 2 * q + 1]);
    const float bias = half ? 0.0f : (bih[g] + bhh[g]);

    if (tid < 256) hs[tid >> 6][tid & 63] = 0.0f;
    if (tid < 2 * RR * 3) {
        int b = tid / (RR * 3), r = (tid / 3) % RR, k = VV + tid % 3;
        xs[b][r][k] = 0.0f;
    }
    if (ldr)
        xs[0][lrow][lv] = x_seq[((size_t)0 * BB + r0 + lrow) * VV + lv];
    float c = 0.0f;
    __syncthreads();

    int cur = 0;
    for (int step = 0; step < TT; step++) {
        // --- issue next-step prefetch EARLY (clamped addr; store guarded) ---
        float xreg = 0.0f;
        {
            int sn = (step + 1 < TT) ? step + 1 : step;
            if (ldr)
                xreg = __ldg(&x_seq[((size_t)sn * BB + r0 + lrow) * VV + lv]);
        }

#pragma unroll
        for (int row = 0; row < RR; row++) {
            const u64* xp = (const u64*)&xs[cur][row][kx0];
            const u64* hp = (const u64*)&hs[row][kh0];
            u64 a0 = 0ull, a1 = 0ull;
#pragma unroll
            for (int q = 0; q < 8; q += 2) {
                a0 = ffma2(wx[q],     xp[q],     a0);
                a1 = ffma2(wx[q + 1], xp[q + 1], a1);
            }
#pragma unroll
            for (int q = 0; q < 16; q += 2) {
                a0 = ffma2(wh[q],     hp[q],     a0);
                a1 = ffma2(wh[q + 1], hp[q + 1], a1);
            }
            float s = f2sum(fadd2(a0, a1)) + bias;
            s += __shfl_xor_sync(0xffffffffu, s, 1);
            if (!half) gs[row][g] = s;
        }
        // --- commit prefetch to the other buffer (LDG latency now hidden) ---
        if (step + 1 < TT && ldr)
            xs[cur ^ 1][lrow][lv] = xreg;
        __syncthreads();

        if (tid < 256) {
            int row = tid >> 6, j = tid & 63;
            float gi = gs[row][j];
            float gf = gs[row][64 + j];
            float gc = gs[row][128 + j];
            float go = gs[row][192 + j];
            c = sigf(gf) * c + sigf(gi) * tanhf_fast(gc);
            float h = sigf(go) * tanhf_fast(c);
            hs[row][j] = h;
            g_y1[((size_t)step * BB + r0 + row) * HH + j] = h;
        }
        __syncthreads();
        cur ^= 1;
    }
}

// ---------------------------------------------------------------------------
// Encoder layer 1: H=64 -> H=64. Same skeleton; y prefetched into registers.
// ---------------------------------------------------------------------------
__global__ __launch_bounds__(512, 1) void enc1_kernel(
    const float* __restrict__ Wih, const float* __restrict__ Whh,
    const float* __restrict__ bih, const float* __restrict__ bhh)
{
    __shared__ __align__(16) float ys[2][RR * HH];
    __shared__ __align__(16) float hs[RR][HH];
    __shared__ float gs[RR][GG];

    const int tid  = threadIdx.x;
    const int g    = tid >> 1;
    const int half = tid & 1;
    const int kh0  = half * 32;
    const int r0   = blockIdx.x * RR;

    u64 wx[16], wh[16];
#pragma unroll
    for (int q = 0; q < 16; q++) {
        wx[q] = pk2(Wih[g * HH + kh0 + 2 * q], Wih[g * HH + kh0 + 2 * q + 1]);
        wh[q] = pk2(Whh[g * HH + kh0 + 2 * q], Whh[g * HH + kh0 + 2 * q + 1]);
    }
    const float bias = half ? 0.0f : (bih[g] + bhh[g]);

    if (tid < 256) hs[tid >> 6][tid & 63] = 0.0f;
    if (tid < 64)
        ((float4*)ys[0])[tid] = ((const float4*)(g_y1 + (size_t)r0 * HH))[tid];
    float c = 0.0f;
    __syncthreads();

    int cur = 0;
    for (int step = 0; step < TT; step++) {
        // --- issue next-step prefetch EARLY ---
        float4 yreg = make_float4(0.f, 0.f, 0.f, 0.f);
        {
            int sn = (step + 1 < TT) ? step + 1 : step;
            if (tid < 64)
                yreg = ((const float4*)(g_y1 + (size_t)sn * BB * HH +
                                        (size_t)r0 * HH))[tid];
        }

#pragma unroll
        for (int row = 0; row < RR; row++) {
            const u64* xp = (const u64*)&ys[cur][row * HH + kh0];
            const u64* hp = (const u64*)&hs[row][kh0];
            u64 a0 = 0ull, a1 = 0ull;
#pragma unroll
            for (int q = 0; q < 16; q += 2) {
                a0 = ffma2(wx[q],     xp[q],     a0);
                a1 = ffma2(wx[q + 1], xp[q + 1], a1);
            }
#pragma unroll
            for (int q = 0; q < 16; q += 2) {
                a0 = ffma2(wh[q],     hp[q],     a0);
                a1 = ffma2(wh[q + 1], hp[q + 1], a1);
            }
            float s = f2sum(fadd2(a0, a1)) + bias;
            s += __shfl_xor_sync(0xffffffffu, s, 1);
            if (!half) gs[row][g] = s;
        }
        if (step + 1 < TT && tid < 64)
            ((float4*)ys[cur ^ 1])[tid] = yreg;
        __syncthreads();

        if (tid < 256) {
            int row = tid >> 6, j = tid & 63;
            float gi = gs[row][j];
            float gf = gs[row][64 + j];
            float gc = gs[row][128 + j];
            float go = gs[row][192 + j];
            c = sigf(gf) * c + sigf(gi) * tanhf_fast(gc);
            float h = sigf(go) * tanhf_fast(c);
            hs[row][j] = h;
            if (step == TT - 1) {
                g_h1[(size_t)r0 * HH + tid] = h;
                g_c1[(size_t)r0 * HH + tid] = c;
            }
        }
        __syncthreads();
        cur ^= 1;
    }
}

// ---------------------------------------------------------------------------
// Decoder: persistent, 128 blocks x 512 threads (R14 structure).
// NEW: letc memoization — mask is uniform across the block, so when it equals
// the previous step's mask the letc table in smem is already correct and the
// letc phase + its barrier are skipped (uniform branch).
// ---------------------------------------------------------------------------
__global__ __launch_bounds__(512, 1) void dec_kernel(
    const float* __restrict__ d1_Wih, const float* __restrict__ d1_Whh,
    const float* __restrict__ d1_bih, const float* __restrict__ d1_bhh,
    const float* __restrict__ d2_Wih, const float* __restrict__ d2_Whh,
    const float* __restrict__ d2_bih, const float* __restrict__ d2_bhh,
    const float* __restrict__ cls_W, const float* __restrict__ cls_b,
    float* __restrict__ out)
{
    __shared__ float wih1T[VV * GG];                 // [j][g] letc table
    __shared__ __align__(16) u64 clsP[32 * 32];      // [kpair][v] packed cls weights
    __shared__ __align__(16) float h1s[RR * HH];
    __shared__ __align__(16) float h2s[RR * HH];
    __shared__ float g1s[RR * GG];
    __shared__ float g2s[RR * GG];
    __shared__ float letc[GG];
    __shared__ __align__(16) float ps[RR * 32];
    __shared__ float clsb[32];
    __shared__ unsigned smaskS;

    const int tid  = threadIdx.x;
    const int g    = tid >> 1;
    const int half = tid & 1;
    const int ko   = half * 32;
    const int r0   = blockIdx.x * RR;

    u64 whh1[16], wih2[16], whh2[16];
#pragma unroll
    for (int q = 0; q < 16; q++) {
        whh1[q] = pk2(d1_Whh[g * HH + ko + 2 * q], d1_Whh[g * HH + ko + 2 * q + 1]);
        wih2[q] = pk2(d2_Wih[g * HH + ko + 2 * q], d2_Wih[g * HH + ko + 2 * q + 1]);
        whh2[q] = pk2(d2_Whh[g * HH + ko + 2 * q], d2_Whh[g * HH + ko + 2 * q + 1]);
    }
    const float bias1 = half ? 0.0f : (d1_bih[g] + d1_bhh[g]);
    const float bias2 = half ? 0.0f : (d2_bih[g] + d2_bhh[g]);

    for (int i = tid; i < VV * GG; i += 512)
        wih1T[(i % VV) * GG + (i / VV)] = d1_Wih[i];
    for (int i = tid; i < VV * 32; i += 512) {
        int v = i >> 5, kk = i & 31;
        clsP[kk * 32 + v] = pk2(cls_W[v * HH + 2 * kk], cls_W[v * HH + 2 * kk + 1]);
    }
    if (tid < VV) clsb[tid] = cls_b[tid];
    if (tid < RR * 3) ps[(tid / 3) * 32 + VV + tid % 3] = -CUDART_INF_F;

    float c;
    if (tid < 256) {
        h1s[tid] = g_h1[(size_t)r0 * HH + tid];
        c        = g_c1[(size_t)r0 * HH + tid];
        h2s[tid] = 0.0f;
    } else {
        c = 0.0f;
    }
    __syncthreads();

    // letc j-range split across the pair
    const int j0 = half ? 15 : 0;
    const int j1 = half ? VV : 15;
    unsigned prev_mask = SENT;          // uniform across block

    for (int step = 0; step < TT; step++) {
        // ---- pre-phase (mask-independent, overlaps the poll wait) ----
        // (a) cell1 pre-gates: bias1 + h1 * Whh1, pair-reduced into g1s
#pragma unroll
        for (int row = 0; row < RR; row++) {
            const u64* hp = (const u64*)&h1s[row * HH + ko];
            u64 a0 = 0ull, a1 = 0ull;
#pragma unroll
            for (int q = 0; q < 16; q += 2) {
                a0 = ffma2(whh1[q],     hp[q],     a0);
                a1 = ffma2(whh1[q + 1], hp[q + 1], a1);
            }
            float s = f2sum(fadd2(a0, a1)) + bias1;
            s += __shfl_xor_sync(0xffffffffu, s, 1);
            if (!half) g1s[row * GG + g] = s;
        }
        // (b) cell2 h2-dot kept in registers
        u64 acc2[RR];
#pragma unroll
        for (int row = 0; row < RR; row++) {
            const u64* hp = (const u64*)&h2s[row * HH + ko];
            u64 a0 = 0ull, a1 = 0ull;
#pragma unroll
            for (int q = 0; q < 16; q += 2) {
                a0 = ffma2(whh2[q],     hp[q],     a0);
                a1 = ffma2(whh2[q + 1], hp[q + 1], a1);
            }
            acc2[row] = fadd2(a0, a1);
        }

        // ---- warp 0 polls this step's 128 slots; others wait at the bar ----
        if (tid < 32) {
            const unsigned* base = g_slots + (size_t)step * NBLK + tid * 4;
            unsigned m;
            for (;;) {
                uint4 v = ld_vol4(base);
                unsigned bad = (v.x == SENT) | (v.y == SENT) |
                               (v.z == SENT) | (v.w == SENT);
                if (!__any_sync(0xffffffffu, bad)) {
                    m = v.x | v.y | v.z | v.w;
                    break;
                }
            }
            m |= __shfl_xor_sync(0xffffffffu, m, 1);
            m |= __shfl_xor_sync(0xffffffffu, m, 2);
            m |= __shfl_xor_sync(0xffffffffu, m, 4);
            m |= __shfl_xor_sync(0xffffffffu, m, 8);
            m |= __shfl_xor_sync(0xffffffffu, m, 16);
            if (tid == 0) smaskS = m;
        }
        __syncthreads();                       // A: mask + g1s visible
        const unsigned mask = smaskS;

        // ---- letc phase: only when mask changed (uniform branch) ----
        if (mask != prev_mask) {
            float ls = 0.0f;
            for (int j = j0; j < j1; j++)
                if ((mask >> j) & 1u) ls += wih1T[j * GG + g];
            ls += __shfl_xor_sync(0xffffffffu, ls, 1);
            if (!half) letc[g] = ls;
            __syncthreads();                   // B: letc ready
        }
        prev_mask = mask;

        // ---- cell1 pointwise (tid<256 owns c1): g1s + letc ----
        if (tid < 256) {
            int row = tid >> 6, j = tid & 63;
            float gi = g1s[row * GG + j]       + letc[j];
            float gf = g1s[row * GG + 64 + j]  + letc[64 + j];
            float gc = g1s[row * GG + 128 + j] + letc[128 + j];
            float go = g1s[row * GG + 192 + j] + letc[192 + j];
            c = sigf(gf) * c + sigf(gi) * tanhf_fast(gc);
            h1s[tid] = sigf(go) * tanhf_fast(c);
        }
        __syncthreads();                       // C: h1 new

        // ---- cell2 gates: h1_new * Wih2 + precomputed h2-dot ----
#pragma unroll
        for (int row = 0; row < RR; row++) {
            const u64* hp = (const u64*)&h1s[row * HH + ko];
            u64 a = acc2[row];
#pragma unroll
            for (int q = 0; q < 16; q++)
                a = ffma2(wih2[q], hp[q], a);
            float s = f2sum(a) + bias2;
            s += __shfl_xor_sync(0xffffffffu, s, 1);
            if (!half) g2s[row * GG + g] = s;
        }
        __syncthreads();                       // D: g2 ready

        // ---- cell2 pointwise (tid>=256 owns c2) ----
        if (tid >= 256) {
            int t2 = tid - 256;
            int row = t2 >> 6, j = t2 & 63;
            float gi = g2s[row * GG + j];
            float gf = g2s[row * GG + 64 + j];
            float gc = g2s[row * GG + 128 + j];
            float go = g2s[row * GG + 192 + j];
            c = sigf(gf) * c + sigf(gi) * tanhf_fast(gc);
            h2s[t2] = sigf(go) * tanhf_fast(c);
        }
        __syncthreads();                       // E: h2 new

        // ---- classifier (tid<256, pair k-split over 116 (row,v) pairs) ----
        if (tid < 256) {
            int p = tid >> 1;
            bool valid = p < RR * VV;
            int pc = valid ? p : 0;
            int row = pc / VV, v = pc - row * VV;
            const u64* hp = (const u64*)&h2s[row * HH] + half * 16;
            u64 a = 0ull;
#pragma unroll
            for (int q = 0; q < 16; q++)
                a = ffma2(clsP[(half * 16 + q) * 32 + v], hp[q], a);
            float s = f2sum(a) + (half ? 0.0f : clsb[v]);
            s += __shfl_xor_sync(0xffffffffu, s, 1);
            if (valid && !half) {
                ps[row * 32 + v] = s;
                out[((size_t)step * BB + r0 + row) * VV + v] = s;
            }
        }
        __syncthreads();                       // F: ps ready

        // ---- argmax (warp 0) + publish this block's slot for step+1 ----
        if (tid < 32) {
            int row = tid >> 3, sl = tid & 7;
            float4 vv = *(const float4*)&ps[row * 32 + sl * 4];
            float best = vv.x; int bi = sl * 4;
            if (vv.y > best) { best = vv.y; bi = sl * 4 + 1; }
            if (vv.z > best) { best = vv.z; bi = sl * 4 + 2; }
            if (vv.w > best) { best = vv.w; bi = sl * 4 + 3; }
#pragma unroll
            for (int off = 1; off <= 4; off <<= 1) {
                float ob = __shfl_xor_sync(0xffffffffu, best, off);
                int   oi = __shfl_xor_sync(0xffffffffu, bi,   off);
                if (ob > best || (ob == best && oi < bi)) { best = ob; bi = oi; }
            }
            unsigned bits = (sl == 0) ? (1u << bi) : 0u;
            bits |= __shfl_xor_sync(0xffffffffu, bits, 8);
            bits |= __shfl_xor_sync(0xffffffffu, bits, 16);
            if (tid == 0)
                st_rel(&g_slots[(size_t)(step + 1) * NBLK + blockIdx.x], bits);
        }
        // no trailing sync: next pre-phase only READS h1s/h2s (stable since
        // bars C/E); g1s rewrite happens after all readers passed bar C.
    }
}

// ---------------------------------------------------------------------------
// Launch
// ---------------------------------------------------------------------------
extern "C" void kernel_launch(void* const* d_in, const int* in_sizes, int n_in,
                              void* d_out, int out_size)
{
    const float* input_seq = (const float*)d_in[0];
    const float* enc_Wih0  = (const float*)d_in[1];
    const float* enc_Whh0  = (const float*)d_in[2];
    const float* enc_bih0  = (const float*)d_in[3];
    const float* enc_bhh0  = (const float*)d_in[4];
    const float* enc_Wih1  = (const float*)d_in[5];
    const float* enc_Whh1  = (const float*)d_in[6];
    const float* enc_bih1  = (const float*)d_in[7];
    const float* enc_bhh1  = (const float*)d_in[8];
    const float* d1_Wih    = (const float*)d_in[9];
    const float* d1_Whh    = (const float*)d_in[10];
    const float* d1_bih    = (const float*)d_in[11];
    const float* d1_bhh    = (const float*)d_in[12];
    const float* d2_Wih    = (const float*)d_in[13];
    const float* d2_Whh    = (const float*)d_in[14];
    const float* d2_bih    = (const float*)d_in[15];
    const float* d2_bhh    = (const float*)d_in[16];
    const float* cls_W     = (const float*)d_in[17];
    const float* cls_b     = (const float*)d_in[18];
    float* out = (float*)d_out;

    init_kernel<<<64, 512>>>();
    enc0_kernel<<<NBLK, 512>>>(input_seq, enc_Wih0, enc_Whh0, enc_bih0, enc_bhh0);
    enc1_kernel<<<NBLK, 512>>>(enc_Wih1, enc_Whh1, enc_bih1, enc_bhh1);
    dec_kernel<<<NBLK, 512>>>(d1_Wih, d1_Whh, d1_bih, d1_bhh,
                              d2_Wih, d2_Whh, d2_bih, d2_bhh,
                              cls_W, cls_b, out);
}